// round 7
// baseline (speedup 1.0000x reference)
#include <cuda_runtime.h>
#include <cuda_bf16.h>
#include <math.h>
#include <stdint.h>

#define N_NODES 30000
#define N_QUADS 7500
#define FDIM    256
#define E_EDGES 480000
#define T_EDGES (E_EDGES + N_NODES)   // 510000
#define HEADS   4
#define HDIM    32
#define HH      128
#define NUM_LABEL 6
#define NEG_SLOPE 0.2f
#define BN_EPS  1e-5f

#define OUT_OFF_LOSS (N_NODES * NUM_LABEL)
#define OUT_OFF_FEAT (OUT_OFF_LOSS + 1)

// ---------------- scratch ----------------------------------------------------
__device__ float g_sum[FDIM];
__device__ float g_sumsq[FDIM];
__device__ __nv_bfloat16 g_Xb[(size_t)N_NODES * 512];   // per row: [hi 256 | lo 256]
__device__ __nv_bfloat16 g_Wb[512 * 256];               // [hi 256 | lo 256] x 256 cols
__device__ float g_bc[256];
__device__ float g_C[(size_t)N_NODES * 256];
__device__ float g_si[N_NODES * HEADS];
__device__ float g_sj[N_NODES * HEADS];
__device__ int   g_deg[N_NODES];
__device__ int   g_off[N_NODES + 1];
__device__ int   g_cur[N_NODES];
__device__ int   g_loc[N_NODES];
__device__ int   g_bsum[32];
__device__ int   g_srcp[T_EDGES];                       // CSR-ordered src
__device__ float g_gat[(size_t)N_NODES * HH];

// ---------------- init --------------------------------------------------------
__global__ void init_kernel(float* out) {
    int i = blockIdx.x * blockDim.x + threadIdx.x;
    if (i < FDIM)                 g_sum[i] = 0.f;
    else if (i < 2 * FDIM)        g_sumsq[i - FDIM] = 0.f;
    else if (i < 2 * FDIM + N_NODES) g_deg[i - 2 * FDIM] = 0;
    else if (i == 2 * FDIM + N_NODES) out[OUT_OFF_LOSS] = 0.f;
}

// ---------------- BN stats + x -> bf16 hi/lo split ----------------------------
__global__ void stats_split_kernel(const float* __restrict__ x) {
    int col = threadIdx.x;
    int r0 = blockIdx.x * 125;
    float s = 0.f, s2 = 0.f;
    #pragma unroll 5
    for (int r = 0; r < 125; r++) {
        int row = r0 + r;
        float v = x[(size_t)row * FDIM + col];
        s += v; s2 += v * v;
        __nv_bfloat16 hi = __float2bfloat16(v);
        __nv_bfloat16 lo = __float2bfloat16(v - __bfloat162float(hi));
        g_Xb[(size_t)row * 512 + col]       = hi;
        g_Xb[(size_t)row * 512 + 256 + col] = lo;
    }
    atomicAdd(&g_sum[col], s);
    atomicAdd(&g_sumsq[col], s2);
}

// ---------------- fold: bn_fin + fold_w + fold_b merged ------------------------
__global__ void fold_all_kernel(const float* __restrict__ W_lin,
                                const float* __restrict__ W_gat,
                                const float* __restrict__ b_lin,
                                const float* __restrict__ gamma,
                                const float* __restrict__ beta) {
    __shared__ float red[256];
    int j = blockIdx.x, k = threadIdx.x;
    float mean = g_sum[k] / (float)N_NODES;
    float var  = g_sumsq[k] / (float)N_NODES - mean * mean;
    float sc = gamma[k] * rsqrtf(var + BN_EPS);
    float sh = beta[k] - mean * sc;
    float wv = (j < 128) ? W_lin[k * 128 + j] : W_gat[k * 128 + j - 128];
    float w = sc * wv;
    __nv_bfloat16 hi = __float2bfloat16(w);
    __nv_bfloat16 lo = __float2bfloat16(w - __bfloat162float(hi));
    g_Wb[k * 256 + j]         = hi;
    g_Wb[(k + 256) * 256 + j] = lo;
    red[k] = sh * wv;
    __syncthreads();
    for (int d = 128; d > 0; d >>= 1) {
        if (k < d) red[k] += red[k + d];
        __syncthreads();
    }
    if (k == 0) g_bc[j] = red[0] + ((j < 128) ? b_lin[j] : 0.f);
}

// ---------------- GEMM: cp.async 3-stage, A-hi reused for Bhi+Blo --------------
// 32 stages: s<16: A=hi[s], B tiles {hi[s], lo[s]}; s>=16: A=lo[s-16], B={hi[s-16]}
#define GSTEPS 32
#define NBUF 3

__global__ __launch_bounds__(256) void gemm_mma_kernel(const float* __restrict__ att) {
    __shared__ __align__(16) char As[NBUF][6144];       // 128 rows x 16 bf16 (pitch 48B)
    __shared__ __align__(16) char Bs[NBUF][2][4352];    // 2 tiles x 16 k-rows x 128 bf16 (pitch 272B)
    __shared__ float bcs[128];

    int tid = threadIdx.x;
    int lane = tid & 31, wid = tid >> 5;
    int wm = wid >> 2, wn = wid & 3;                    // 2 x 4 warp grid
    int row0 = blockIdx.y * 128, col0 = blockIdx.x * 128;

    if (tid < 128) bcs[tid] = g_bc[col0 + tid];

    int arow = tid >> 1, ahalf = tid & 1;
    bool avalid = (row0 + arow) < N_NODES;
    int asz = avalid ? 16 : 0;
    const char* agbase = (const char*)(g_Xb + (size_t)(row0 + arow) * 512 + ahalf * 8);
    int bkrow = tid >> 4, bnc = (tid & 15) * 8;
    const __nv_bfloat16* bg1 = g_Wb + bkrow * 256 + col0 + bnc;
    const __nv_bfloat16* bg2 = bg1 + 256 * 256;

    uint32_t asw = (uint32_t)__cvta_generic_to_shared(&As[0][0]);
    uint32_t bsw = (uint32_t)__cvta_generic_to_shared(&Bs[0][0][0]);
    uint32_t adst = asw + arow * 48 + ahalf * 16;
    uint32_t bdst = bsw + bkrow * 272 + bnc * 2;

#define CPA(dst, src, sz) \
    asm volatile("cp.async.cg.shared.global [%0], [%1], 16, %2;" \
                 :: "r"(dst), "l"(src), "r"(sz))

#define ISSUE(s, buf) do { \
    if ((s) < GSTEPS) { \
        int aoff2 = (((((s) >> 4) & 1) * 256) + ((s) & 15) * 16) * 2; \
        CPA(adst + (buf) * 6144, agbase + aoff2, asz); \
        CPA(bdst + (buf) * 8704, (const char*)(bg1 + ((s) & 15) * 16 * 256), 16); \
        if ((s) < 16) \
            CPA(bdst + (buf) * 8704 + 4352, (const char*)(bg2 + (s) * 16 * 256), 16); \
    } \
    asm volatile("cp.async.commit_group;"); \
} while (0)

    ISSUE(0, 0);
    ISSUE(1, 1);

    float acc[4][4][4];
    #pragma unroll
    for (int a = 0; a < 4; a++)
        #pragma unroll
        for (int b = 0; b < 4; b++)
            #pragma unroll
            for (int c = 0; c < 4; c++) acc[a][b][c] = 0.f;

    for (int s = 0; s < GSTEPS; s++) {
        int cb = s % 3;
        asm volatile("cp.async.wait_group 1;");
        __syncthreads();
        ISSUE(s + 2, (s + 2) % 3);

        uint32_t abuf = asw + cb * 6144;
        uint32_t afr[4][4];
        #pragma unroll
        for (int im = 0; im < 4; im++) {
            uint32_t ad = abuf + (wm * 64 + im * 16 + (lane & 15)) * 48 + (lane >> 4) * 16;
            asm volatile("ldmatrix.sync.aligned.m8n8.x4.shared.b16 {%0,%1,%2,%3}, [%4];"
                : "=r"(afr[im][0]), "=r"(afr[im][1]), "=r"(afr[im][2]), "=r"(afr[im][3]) : "r"(ad));
        }
        int ntile = (s < 16) ? 2 : 1;
        #pragma unroll
        for (int t = 0; t < 2; t++) {
            if (t >= ntile) break;
            uint32_t bbuf = bsw + cb * 8704 + t * 4352;
            uint32_t bfr[4][2];
            #pragma unroll
            for (int half = 0; half < 2; half++) {
                uint32_t ad = bbuf + (lane & 15) * 272 + (wn * 32 + half * 16 + (lane >> 4) * 8) * 2;
                uint32_t r0, r1, r2, r3;
                asm volatile("ldmatrix.sync.aligned.m8n8.x4.trans.shared.b16 {%0,%1,%2,%3}, [%4];"
                    : "=r"(r0), "=r"(r1), "=r"(r2), "=r"(r3) : "r"(ad));
                bfr[half*2][0] = r0; bfr[half*2][1] = r1;
                bfr[half*2+1][0] = r2; bfr[half*2+1][1] = r3;
            }
            #pragma unroll
            for (int im = 0; im < 4; im++)
                #pragma unroll
                for (int in = 0; in < 4; in++) {
                    asm volatile(
                        "mma.sync.aligned.m16n8k16.row.col.f32.bf16.bf16.f32 "
                        "{%0,%1,%2,%3}, {%4,%5,%6,%7}, {%8,%9}, {%0,%1,%2,%3};"
                        : "+f"(acc[im][in][0]), "+f"(acc[im][in][1]),
                          "+f"(acc[im][in][2]), "+f"(acc[im][in][3])
                        : "r"(afr[im][0]), "r"(afr[im][1]), "r"(afr[im][2]), "r"(afr[im][3]),
                          "r"(bfr[in][0]), "r"(bfr[in][1]));
                }
        }
    }

    // ---- epilogue (+ fused attention dots for the xt half)
    bool xt_half = (col0 == 128);
    int h = wn;
    const float* ai = att + h * 64;
    const float* aj = att + h * 64 + 32;

    #pragma unroll
    for (int im = 0; im < 4; im++) {
        int r = row0 + wm * 64 + im * 16 + (lane >> 2);
        float psi0 = 0.f, psj0 = 0.f, psi1 = 0.f, psj1 = 0.f;
        #pragma unroll
        for (int in = 0; in < 4; in++) {
            int crel = wn * 32 + in * 8 + (lane & 3) * 2;
            int c = col0 + crel;
            float v00 = acc[im][in][0] + bcs[crel];
            float v01 = acc[im][in][1] + bcs[crel + 1];
            float v10 = acc[im][in][2] + bcs[crel];
            float v11 = acc[im][in][3] + bcs[crel + 1];
            if (r < N_NODES)
                *(float2*)&g_C[(size_t)r * 256 + c] = make_float2(v00, v01);
            if (r + 8 < N_NODES)
                *(float2*)&g_C[(size_t)(r + 8) * 256 + c] = make_float2(v10, v11);
            if (xt_half) {
                int cl = in * 8 + (lane & 3) * 2;
                float ai0 = ai[cl], ai1 = ai[cl + 1];
                float aj0 = aj[cl], aj1 = aj[cl + 1];
                psi0 += v00 * ai0 + v01 * ai1;
                psj0 += v00 * aj0 + v01 * aj1;
                psi1 += v10 * ai0 + v11 * ai1;
                psj1 += v10 * aj0 + v11 * aj1;
            }
        }
        if (xt_half) {
            #pragma unroll
            for (int d = 1; d <= 2; d <<= 1) {
                psi0 += __shfl_xor_sync(0xffffffffu, psi0, d);
                psj0 += __shfl_xor_sync(0xffffffffu, psj0, d);
                psi1 += __shfl_xor_sync(0xffffffffu, psi1, d);
                psj1 += __shfl_xor_sync(0xffffffffu, psj1, d);
            }
            if ((lane & 3) == 0) {
                if (r < N_NODES)     { g_si[r * 4 + h] = psi0; g_sj[r * 4 + h] = psj0; }
                if (r + 8 < N_NODES) { g_si[(r + 8) * 4 + h] = psi1; g_sj[(r + 8) * 4 + h] = psj1; }
            }
        }
    }
}

// ---------------- CSR build (multi-block scan) -----------------------------------
__global__ void deg_kernel(const int* __restrict__ dst) {
    int e = blockIdx.x * blockDim.x + threadIdx.x;
    if (e >= T_EDGES) return;
    int d = (e < E_EDGES) ? dst[e] : (e - E_EDGES);
    atomicAdd(&g_deg[d], 1);
}

__global__ void scanA_kernel() {
    __shared__ int wsum[32];
    int t = threadIdx.x, b = blockIdx.x;
    int i = b * 1024 + t;
    int lane = t & 31, wr = t >> 5;
    int v = (i < N_NODES) ? g_deg[i] : 0;
    int incl = v;
    #pragma unroll
    for (int d = 1; d < 32; d <<= 1) {
        int tt = __shfl_up_sync(0xffffffffu, incl, d);
        if (lane >= d) incl += tt;
    }
    if (lane == 31) wsum[wr] = incl;
    __syncthreads();
    if (wr == 0) {
        int wv = wsum[lane];
        #pragma unroll
        for (int d = 1; d < 32; d <<= 1) {
            int tt = __shfl_up_sync(0xffffffffu, wv, d);
            if (lane >= d) wv += tt;
        }
        wsum[lane] = wv;
    }
    __syncthreads();
    int base = (wr > 0) ? wsum[wr - 1] : 0;
    incl += base;
    if (i < N_NODES) g_loc[i] = incl;
    if (t == 1023) g_bsum[b] = incl;
}

__global__ void scanB_kernel() {
    int t = threadIdx.x;
    int v = (t < 30) ? g_bsum[t] : 0;
    int incl = v;
    #pragma unroll
    for (int d = 1; d < 32; d <<= 1) {
        int tt = __shfl_up_sync(0xffffffffu, incl, d);
        if (t >= d) incl += tt;
    }
    g_bsum[t] = incl - v;
    if (t == 31) g_off[N_NODES] = incl;
}

__global__ void scanC_kernel() {
    int i = blockIdx.x * 1024 + threadIdx.x;
    if (i >= N_NODES) return;
    int off = g_bsum[blockIdx.x] + g_loc[i] - g_deg[i];
    g_off[i] = off;
    g_cur[i] = off;
}

__global__ void scatter_kernel(const int* __restrict__ src,
                               const int* __restrict__ dst) {
    int e = blockIdx.x * blockDim.x + threadIdx.x;
    if (e >= T_EDGES) return;
    int s, d;
    if (e < E_EDGES) { s = src[e]; d = dst[e]; }
    else             { s = d = e - E_EDGES; }
    int pos = atomicAdd(&g_cur[d], 1);
    g_srcp[pos] = s;
}

// ---------------- segment softmax + aggregation (warp per node-head) ------------
__global__ __launch_bounds__(256) void aggr_kernel(const float* __restrict__ b_gat) {
    int gw = (blockIdx.x * 256 + threadIdx.x) >> 5;
    int lane = threadIdx.x & 31;
    if (gw >= N_NODES * HEADS) return;
    int n = gw >> 2, h = gw & 3;
    int beg = g_off[n], end = g_off[n + 1];
    float si = g_si[n * 4 + h];

    float m = -1e30f;
    for (int j = beg + lane; j < end; j += 32) {
        int s = g_srcp[j];
        float a = si + g_sj[s * 4 + h];
        a = (a >= 0.f) ? a : NEG_SLOPE * a;
        m = fmaxf(m, a);
    }
    #pragma unroll
    for (int d = 16; d > 0; d >>= 1)
        m = fmaxf(m, __shfl_xor_sync(0xffffffffu, m, d));

    float den = 0.f, acc = 0.f;
    #pragma unroll 4
    for (int j = beg; j < end; j++) {
        int s = g_srcp[j];
        float a = si + g_sj[s * 4 + h];
        a = (a >= 0.f) ? a : NEG_SLOPE * a;
        float e = __expf(a - m);
        acc += e * g_C[(size_t)s * 256 + 128 + h * 32 + lane];
        den += e;
    }
    float r = acc / (den + 1e-16f) + b_gat[h * 32 + lane];
    g_gat[(size_t)n * HH + h * 32 + lane] = fmaxf(r, 0.f);
}

// ---------------- capsule + routing: 4 nodes/warp, per-class loop ----------------
#define CWARPS 10
#define WARP_FLOATS (1056 + 512)   // tmp 32x33 + u 4x128
#define CAP_SMEM_FLOATS (24576 + 512 + 16 + CWARPS * WARP_FLOATS + CWARPS * 24)

__device__ __forceinline__ float warp_sum32(float t) {
    t += __shfl_xor_sync(0xffffffffu, t, 1);
    t += __shfl_xor_sync(0xffffffffu, t, 2);
    t += __shfl_xor_sync(0xffffffffu, t, 4);
    t += __shfl_xor_sync(0xffffffffu, t, 8);
    t += __shfl_xor_sync(0xffffffffu, t, 16);
    return t;
}

__global__ __launch_bounds__(CWARPS * 32, 1)
void capsule_kernel(const float* __restrict__ Wp, const float* __restrict__ bp,
                    const float* __restrict__ route_w, const int* __restrict__ y,
                    float* __restrict__ out) {
    extern __shared__ float sh[];
    float4* rw4 = (float4*)sh;                         // 24576 floats (96KB)
    float* wps = sh + 24576;                           // 512
    float* bps = wps + 512;                            // 16
    float* warpb = bps + 16;                           // CWARPS * 1568
    float* nshm  = warpb + CWARPS * WARP_FLOATS;       // CWARPS * 24
    __shared__ float blockLoss;

    int tid = threadIdx.x, lane = tid & 31, w = tid >> 5;

    // repack route_w: rw4[(pair*2+kq)*32 + lane] = {w[k..k+3] at o=lane}, k=4*kq
    for (int i4 = tid; i4 < 6144; i4 += CWARPS * 32) {
        int pair = i4 >> 6;
        int rem = i4 & 63;
        int kq = rem >> 5, ln = rem & 31;
        int base = (pair * 8 + kq * 4) * 32 + ln;
        rw4[i4] = make_float4(route_w[base], route_w[base + 32],
                              route_w[base + 64], route_w[base + 96]);
    }
    for (int i = tid; i < 512; i += CWARPS * 32) wps[i] = Wp[i];
    if (tid < 16) bps[tid] = bp[tid];
    if (tid == 0) blockLoss = 0.f;
    __syncthreads();

    float* tmp = warpb + w * WARP_FLOATS;   // 1056: xc (4x264) / transpose (32x33)
    float* uwb = tmp + 1056;                // 512: u for 4 nodes
    float* ncw = nshm + w * 24;

    for (int q = blockIdx.x * CWARPS + w; q < N_QUADS; q += gridDim.x * CWARPS) {
        int nb = 4 * q;

        // ---- xc = relu(concat(gat, hidden)), 4 nodes
        #pragma unroll
        for (int nd = 0; nd < 4; nd++) {
            int n = nb + nd;
            #pragma unroll
            for (int r = 0; r < 8; r++) {
                float v = (r < 4)
                    ? g_gat[(size_t)n * HH + r * 32 + lane]
                    : fmaxf(g_C[(size_t)n * 256 + (r - 4) * 32 + lane], 0.f);
                tmp[nd * 264 + r * 33 + lane] = v;
            }
        }
        __syncwarp();

        // ---- primary capsules -> u (4 nodes); pc phase only READS tmp
        #pragma unroll
        for (int nd = 0; nd < 4; nd++) {
            const float* xcn = tmp + nd * 264;
            float* uw = uwb + nd * 128;
            #pragma unroll
            for (int qq = 0; qq < 4; qq++) {
                int idx = lane + 32 * qq;
                int c = idx >> 6, r = (idx >> 3) & 7, o = idx & 7;
                float acc = bps[c * 8 + o];
                #pragma unroll
                for (int hh = 0; hh < 32; hh++)
                    acc += xcn[r * 33 + hh] * wps[(c * 32 + hh) * 8 + o];
                float t = acc * acc;
                t += __shfl_xor_sync(0xffffffffu, t, 1);
                t += __shfl_xor_sync(0xffffffffu, t, 2);
                t += __shfl_xor_sync(0xffffffffu, t, 4);
                uw[idx] = acc * sqrtf(t) / (1.f + t);
            }
        }
        __syncwarp();

        // ---- per-class priors + routing (lane = o)
        for (int c2 = 0; c2 < 6; c2++) {
            float pr[4][16];
            #pragma unroll
            for (int rr = 0; rr < 16; rr++) {
                int pair = c2 * 16 + rr;
                float4 f0 = rw4[(pair * 2 + 0) * 32 + lane];
                float4 f1 = rw4[(pair * 2 + 1) * 32 + lane];
                #pragma unroll
                for (int nd = 0; nd < 4; nd++) {
                    float4 a = *(const float4*)&uwb[nd * 128 + rr * 8];
                    float4 b = *(const float4*)&uwb[nd * 128 + rr * 8 + 4];
                    pr[nd][rr] = a.x * f0.x + a.y * f0.y + a.z * f0.z + a.w * f0.w
                               + b.x * f1.x + b.y * f1.y + b.z * f1.z + b.w * f1.w;
                }
            }

            // it 0: probs uniform -> v = mean_r priors
            float v[4], vo[4], sq[4], norm[4];
            #pragma unroll
            for (int nd = 0; nd < 4; nd++) {
                float s = 0.f;
                #pragma unroll
                for (int rr = 0; rr < 16; rr++) s += pr[nd][rr];
                v[nd] = s * 0.0625f;
                sq[nd] = warp_sum32(v[nd] * v[nd]);
                vo[nd] = v[nd] * sqrtf(sq[nd]) / (1.f + sq[nd]);
            }

            // logits distributed: bd01 lane<16->node0 r=lane, else node1;
            //                     bd23 same for nodes 2,3
            float bd01, bd23;
            __syncwarp();
            {
                #pragma unroll
                for (int rr = 0; rr < 16; rr++) {
                    tmp[rr * 33 + lane]        = pr[0][rr] * vo[0];
                    tmp[(16 + rr) * 33 + lane] = pr[1][rr] * vo[1];
                }
                __syncwarp();
                const float* row = tmp + ((lane & 15) + (lane >> 4) * 16) * 33;
                float s = 0.f;
                #pragma unroll
                for (int o = 0; o < 32; o++) s += row[o];
                bd01 = s;
                __syncwarp();
                #pragma unroll
                for (int rr = 0; rr < 16; rr++) {
                    tmp[rr * 33 + lane]        = pr[2][rr] * vo[2];
                    tmp[(16 + rr) * 33 + lane] = pr[3][rr] * vo[3];
                }
                __syncwarp();
                s = 0.f;
                #pragma unroll
                for (int o = 0; o < 32; o++) s += row[o];
                bd23 = s;
                __syncwarp();
            }

            #pragma unroll
            for (int it = 1; it < 3; it++) {
                // softmax over r within 16-lane halves (no max-subtract; |b| small)
                float e01 = __expf(bd01), e23 = __expf(bd23);
                float es01 = e01, es23 = e23;
                #pragma unroll
                for (int d = 1; d <= 8; d <<= 1) {
                    es01 += __shfl_xor_sync(0xffffffffu, es01, d);
                    es23 += __shfl_xor_sync(0xffffffffu, es23, d);
                }
                float pp01 = __fdividef(e01, es01);
                float pp23 = __fdividef(e23, es23);
                v[0] = v[1] = v[2] = v[3] = 0.f;
                #pragma unroll
                for (int rr = 0; rr < 16; rr++) {
                    float p0 = __shfl_sync(0xffffffffu, pp01, rr);
                    float p1 = __shfl_sync(0xffffffffu, pp01, 16 + rr);
                    float p2 = __shfl_sync(0xffffffffu, pp23, rr);
                    float p3 = __shfl_sync(0xffffffffu, pp23, 16 + rr);
                    v[0] += p0 * pr[0][rr];
                    v[1] += p1 * pr[1][rr];
                    v[2] += p2 * pr[2][rr];
                    v[3] += p3 * pr[3][rr];
                }
                #pragma unroll
                for (int nd = 0; nd < 4; nd++) {
                    sq[nd] = warp_sum32(v[nd] * v[nd]);
                    vo[nd] = v[nd] * sqrtf(sq[nd]) / (1.f + sq[nd]);
                }
                if (it == 1) {
                    __syncwarp();
                    #pragma unroll
                    for (int rr = 0; rr < 16; rr++) {
                        tmp[rr * 33 + lane]        = pr[0][rr] * vo[0];
                        tmp[(16 + rr) * 33 + lane] = pr[1][rr] * vo[1];
                    }
                    __syncwarp();
                    const float* row = tmp + ((lane & 15) + (lane >> 4) * 16) * 33;
                    float s = 0.f;
                    #pragma unroll
                    for (int o = 0; o < 32; o++) s += row[o];
                    bd01 += s;
                    __syncwarp();
                    #pragma unroll
                    for (int rr = 0; rr < 16; rr++) {
                        tmp[rr * 33 + lane]        = pr[2][rr] * vo[2];
                        tmp[(16 + rr) * 33 + lane] = pr[3][rr] * vo[3];
                    }
                    __syncwarp();
                    s = 0.f;
                    #pragma unroll
                    for (int o = 0; o < 32; o++) s += row[o];
                    bd23 += s;
                    __syncwarp();
                } else {
                    #pragma unroll
                    for (int nd = 0; nd < 4; nd++) norm[nd] = sq[nd] / (1.f + sq[nd]);
                }
            }

            #pragma unroll
            for (int nd = 0; nd < 4; nd++)
                out[OUT_OFF_FEAT + (size_t)(nb + nd) * (NUM_LABEL * HDIM) + c2 * 32 + lane] = vo[nd];
            if (lane == 0) {
                #pragma unroll
                for (int nd = 0; nd < 4; nd++) ncw[nd * 6 + c2] = norm[nd];
            }
        }
        __syncwarp();

        // ---- per-node log-softmax loss + normc output (lanes 0,8,16,24)
        if ((lane & 7) == 0) {
            int nd = lane >> 3;
            int n = nb + nd;
            const float* nc = ncw + nd * 6;
            float mx = nc[0];
            #pragma unroll
            for (int c = 1; c < 6; c++) mx = fmaxf(mx, nc[c]);
            float sm = 0.f;
            #pragma unroll
            for (int c = 0; c < 6; c++) sm += __expf(nc[c] - mx);
            float lse = mx + logf(sm);
            float sel = nc[y[n]];
            #pragma unroll
            for (int c = 0; c < 6; c++) out[(size_t)n * 6 + c] = nc[c];
            atomicAdd(&blockLoss, lse - sel);
        }
        __syncwarp();
    }
    __syncthreads();
    if (tid == 0) atomicAdd(&out[OUT_OFF_LOSS], blockLoss / (float)N_NODES);
}

// ---------------- launch ---------------------------------------------------------
extern "C" void kernel_launch(void* const* d_in, const int* in_sizes, int n_in,
                              void* d_out, int out_size) {
    const float* x       = (const float*)d_in[0];
    const float* gamma   = (const float*)d_in[1];
    const float* beta    = (const float*)d_in[2];
    const float* W_lin   = (const float*)d_in[3];
    const float* b_lin   = (const float*)d_in[4];
    const float* W_gat   = (const float*)d_in[5];
    const float* att     = (const float*)d_in[6];
    const float* b_gat   = (const float*)d_in[7];
    const float* Wp      = (const float*)d_in[8];
    const float* bp      = (const float*)d_in[9];
    const float* route_w = (const float*)d_in[10];
    const int*   eidx    = (const int*)d_in[11];
    const int*   y       = (const int*)d_in[12];
    float* out = (float*)d_out;

    const int* src = eidx;
    const int* dst = eidx + E_EDGES;

    init_kernel<<<(2 * FDIM + N_NODES + 256) / 256, 256>>>(out);
    stats_split_kernel<<<240, 256>>>(x);
    fold_all_kernel<<<256, 256>>>(W_lin, W_gat, b_lin, gamma, beta);

    gemm_mma_kernel<<<dim3(2, (N_NODES + 127) / 128), 256>>>(att);

    deg_kernel<<<(T_EDGES + 255) / 256, 256>>>(dst);
    scanA_kernel<<<30, 1024>>>();
    scanB_kernel<<<1, 32>>>();
    scanC_kernel<<<30, 1024>>>();
    scatter_kernel<<<(T_EDGES + 255) / 256, 256>>>(src, dst);
    aggr_kernel<<<(N_NODES * HEADS + 7) / 8, 256>>>(b_gat);

    static const size_t cap_smem = (size_t)CAP_SMEM_FLOATS * sizeof(float);
    cudaFuncSetAttribute(capsule_kernel,
                         cudaFuncAttributeMaxDynamicSharedMemorySize,
                         (int)cap_smem);
    capsule_kernel<<<148, CWARPS * 32, cap_smem>>>(Wp, bp, route_w, y, out);
}

// round 8
// speedup vs baseline: 1.0564x; 1.0564x over previous
#include <cuda_runtime.h>
#include <cuda_bf16.h>
#include <math.h>
#include <stdint.h>

#define N_NODES 30000
#define N_PAIRS 15000
#define FDIM    256
#define E_EDGES 480000
#define T_EDGES (E_EDGES + N_NODES)   // 510000
#define HEADS   4
#define HDIM    32
#define HH      128
#define NUM_LABEL 6
#define NEG_SLOPE 0.2f
#define BN_EPS  1e-5f

#define OUT_OFF_LOSS (N_NODES * NUM_LABEL)
#define OUT_OFF_FEAT (OUT_OFF_LOSS + 1)

// ---------------- scratch ----------------------------------------------------
__device__ float g_sum[FDIM];
__device__ float g_sumsq[FDIM];
__device__ __nv_bfloat16 g_Xb[(size_t)N_NODES * 512];   // per row: [hi 256 | lo 256]
__device__ __nv_bfloat16 g_Wb[512 * 256];               // [hi 256 | lo 256] x 256 cols
__device__ float g_bc[256];
__device__ float g_C[(size_t)N_NODES * 256];
__device__ float g_si[N_NODES * HEADS];
__device__ float g_sj[N_NODES * HEADS];
__device__ int   g_deg[N_NODES];
__device__ int   g_off[N_NODES + 1];
__device__ int   g_cur[N_NODES];
__device__ int   g_loc[N_NODES];
__device__ int   g_bsum[32];
__device__ int   g_srcp[T_EDGES];                       // CSR-ordered src
__device__ float g_gat[(size_t)N_NODES * HH];

// ---------------- init --------------------------------------------------------
__global__ void init_kernel(float* out) {
    int i = blockIdx.x * blockDim.x + threadIdx.x;
    if (i < FDIM)                 g_sum[i] = 0.f;
    else if (i < 2 * FDIM)        g_sumsq[i - FDIM] = 0.f;
    else if (i < 2 * FDIM + N_NODES) g_deg[i - 2 * FDIM] = 0;
    else if (i == 2 * FDIM + N_NODES) out[OUT_OFF_LOSS] = 0.f;
}

// ---------------- BN stats + x -> bf16 hi/lo split ----------------------------
__global__ void stats_split_kernel(const float* __restrict__ x) {
    int col = threadIdx.x;
    int r0 = blockIdx.x * 125;
    float s = 0.f, s2 = 0.f;
    #pragma unroll 5
    for (int r = 0; r < 125; r++) {
        int row = r0 + r;
        float v = x[(size_t)row * FDIM + col];
        s += v; s2 += v * v;
        __nv_bfloat16 hi = __float2bfloat16(v);
        __nv_bfloat16 lo = __float2bfloat16(v - __bfloat162float(hi));
        g_Xb[(size_t)row * 512 + col]       = hi;
        g_Xb[(size_t)row * 512 + 256 + col] = lo;
    }
    atomicAdd(&g_sum[col], s);
    atomicAdd(&g_sumsq[col], s2);
}

// ---------------- fold: bn_fin + fold_w + fold_b merged ------------------------
__global__ void fold_all_kernel(const float* __restrict__ W_lin,
                                const float* __restrict__ W_gat,
                                const float* __restrict__ b_lin,
                                const float* __restrict__ gamma,
                                const float* __restrict__ beta) {
    __shared__ float red[256];
    int j = blockIdx.x, k = threadIdx.x;
    float mean = g_sum[k] / (float)N_NODES;
    float var  = g_sumsq[k] / (float)N_NODES - mean * mean;
    float sc = gamma[k] * rsqrtf(var + BN_EPS);
    float sh = beta[k] - mean * sc;
    float wv = (j < 128) ? W_lin[k * 128 + j] : W_gat[k * 128 + j - 128];
    float w = sc * wv;
    __nv_bfloat16 hi = __float2bfloat16(w);
    __nv_bfloat16 lo = __float2bfloat16(w - __bfloat162float(hi));
    g_Wb[k * 256 + j]         = hi;
    g_Wb[(k + 256) * 256 + j] = lo;
    red[k] = sh * wv;
    __syncthreads();
    for (int d = 128; d > 0; d >>= 1) {
        if (k < d) red[k] += red[k + d];
        __syncthreads();
    }
    if (k == 0) g_bc[j] = red[0] + ((j < 128) ? b_lin[j] : 0.f);
}

// ---------------- GEMM: cp.async 3-stage, A-hi reused for Bhi+Blo --------------
// 32 stages: s<16: A=hi[s], B tiles {hi[s], lo[s]}; s>=16: A=lo[s-16], B={hi[s-16]}
#define GSTEPS 32
#define NBUF 3

__global__ __launch_bounds__(256) void gemm_mma_kernel(const float* __restrict__ att) {
    __shared__ __align__(16) char As[NBUF][6144];       // 128 rows x 16 bf16 (pitch 48B)
    __shared__ __align__(16) char Bs[NBUF][2][4352];    // 2 tiles x 16 k-rows x 128 bf16 (pitch 272B)
    __shared__ float bcs[128];

    int tid = threadIdx.x;
    int lane = tid & 31, wid = tid >> 5;
    int wm = wid >> 2, wn = wid & 3;                    // 2 x 4 warp grid
    int row0 = blockIdx.y * 128, col0 = blockIdx.x * 128;

    if (tid < 128) bcs[tid] = g_bc[col0 + tid];

    int arow = tid >> 1, ahalf = tid & 1;
    bool avalid = (row0 + arow) < N_NODES;
    int asz = avalid ? 16 : 0;
    const char* agbase = (const char*)(g_Xb + (size_t)(row0 + arow) * 512 + ahalf * 8);
    int bkrow = tid >> 4, bnc = (tid & 15) * 8;
    const __nv_bfloat16* bg1 = g_Wb + bkrow * 256 + col0 + bnc;
    const __nv_bfloat16* bg2 = bg1 + 256 * 256;

    uint32_t asw = (uint32_t)__cvta_generic_to_shared(&As[0][0]);
    uint32_t bsw = (uint32_t)__cvta_generic_to_shared(&Bs[0][0][0]);
    uint32_t adst = asw + arow * 48 + ahalf * 16;
    uint32_t bdst = bsw + bkrow * 272 + bnc * 2;

#define CPA(dst, src, sz) \
    asm volatile("cp.async.cg.shared.global [%0], [%1], 16, %2;" \
                 :: "r"(dst), "l"(src), "r"(sz))

#define ISSUE(s, buf) do { \
    if ((s) < GSTEPS) { \
        int aoff2 = (((((s) >> 4) & 1) * 256) + ((s) & 15) * 16) * 2; \
        CPA(adst + (buf) * 6144, agbase + aoff2, asz); \
        CPA(bdst + (buf) * 8704, (const char*)(bg1 + ((s) & 15) * 16 * 256), 16); \
        if ((s) < 16) \
            CPA(bdst + (buf) * 8704 + 4352, (const char*)(bg2 + (s) * 16 * 256), 16); \
    } \
    asm volatile("cp.async.commit_group;"); \
} while (0)

    ISSUE(0, 0);
    ISSUE(1, 1);

    float acc[4][4][4];
    #pragma unroll
    for (int a = 0; a < 4; a++)
        #pragma unroll
        for (int b = 0; b < 4; b++)
            #pragma unroll
            for (int c = 0; c < 4; c++) acc[a][b][c] = 0.f;

    for (int s = 0; s < GSTEPS; s++) {
        int cb = s % 3;
        asm volatile("cp.async.wait_group 1;");
        __syncthreads();
        ISSUE(s + 2, (s + 2) % 3);

        uint32_t abuf = asw + cb * 6144;
        uint32_t afr[4][4];
        #pragma unroll
        for (int im = 0; im < 4; im++) {
            uint32_t ad = abuf + (wm * 64 + im * 16 + (lane & 15)) * 48 + (lane >> 4) * 16;
            asm volatile("ldmatrix.sync.aligned.m8n8.x4.shared.b16 {%0,%1,%2,%3}, [%4];"
                : "=r"(afr[im][0]), "=r"(afr[im][1]), "=r"(afr[im][2]), "=r"(afr[im][3]) : "r"(ad));
        }
        int ntile = (s < 16) ? 2 : 1;
        #pragma unroll
        for (int t = 0; t < 2; t++) {
            if (t >= ntile) break;
            uint32_t bbuf = bsw + cb * 8704 + t * 4352;
            uint32_t bfr[4][2];
            #pragma unroll
            for (int half = 0; half < 2; half++) {
                uint32_t ad = bbuf + (lane & 15) * 272 + (wn * 32 + half * 16 + (lane >> 4) * 8) * 2;
                uint32_t r0, r1, r2, r3;
                asm volatile("ldmatrix.sync.aligned.m8n8.x4.trans.shared.b16 {%0,%1,%2,%3}, [%4];"
                    : "=r"(r0), "=r"(r1), "=r"(r2), "=r"(r3) : "r"(ad));
                bfr[half*2][0] = r0; bfr[half*2][1] = r1;
                bfr[half*2+1][0] = r2; bfr[half*2+1][1] = r3;
            }
            #pragma unroll
            for (int im = 0; im < 4; im++)
                #pragma unroll
                for (int in = 0; in < 4; in++) {
                    asm volatile(
                        "mma.sync.aligned.m16n8k16.row.col.f32.bf16.bf16.f32 "
                        "{%0,%1,%2,%3}, {%4,%5,%6,%7}, {%8,%9}, {%0,%1,%2,%3};"
                        : "+f"(acc[im][in][0]), "+f"(acc[im][in][1]),
                          "+f"(acc[im][in][2]), "+f"(acc[im][in][3])
                        : "r"(afr[im][0]), "r"(afr[im][1]), "r"(afr[im][2]), "r"(afr[im][3]),
                          "r"(bfr[in][0]), "r"(bfr[in][1]));
                }
        }
    }

    // ---- epilogue (+ fused attention dots for the xt half)
    bool xt_half = (col0 == 128);
    int h = wn;
    const float* ai = att + h * 64;
    const float* aj = att + h * 64 + 32;

    #pragma unroll
    for (int im = 0; im < 4; im++) {
        int r = row0 + wm * 64 + im * 16 + (lane >> 2);
        float psi0 = 0.f, psj0 = 0.f, psi1 = 0.f, psj1 = 0.f;
        #pragma unroll
        for (int in = 0; in < 4; in++) {
            int crel = wn * 32 + in * 8 + (lane & 3) * 2;
            int c = col0 + crel;
            float v00 = acc[im][in][0] + bcs[crel];
            float v01 = acc[im][in][1] + bcs[crel + 1];
            float v10 = acc[im][in][2] + bcs[crel];
            float v11 = acc[im][in][3] + bcs[crel + 1];
            if (r < N_NODES)
                *(float2*)&g_C[(size_t)r * 256 + c] = make_float2(v00, v01);
            if (r + 8 < N_NODES)
                *(float2*)&g_C[(size_t)(r + 8) * 256 + c] = make_float2(v10, v11);
            if (xt_half) {
                int cl = in * 8 + (lane & 3) * 2;
                float ai0 = ai[cl], ai1 = ai[cl + 1];
                float aj0 = aj[cl], aj1 = aj[cl + 1];
                psi0 += v00 * ai0 + v01 * ai1;
                psj0 += v00 * aj0 + v01 * aj1;
                psi1 += v10 * ai0 + v11 * ai1;
                psj1 += v10 * aj0 + v11 * aj1;
            }
        }
        if (xt_half) {
            #pragma unroll
            for (int d = 1; d <= 2; d <<= 1) {
                psi0 += __shfl_xor_sync(0xffffffffu, psi0, d);
                psj0 += __shfl_xor_sync(0xffffffffu, psj0, d);
                psi1 += __shfl_xor_sync(0xffffffffu, psi1, d);
                psj1 += __shfl_xor_sync(0xffffffffu, psj1, d);
            }
            if ((lane & 3) == 0) {
                if (r < N_NODES)     { g_si[r * 4 + h] = psi0; g_sj[r * 4 + h] = psj0; }
                if (r + 8 < N_NODES) { g_si[(r + 8) * 4 + h] = psi1; g_sj[(r + 8) * 4 + h] = psj1; }
            }
        }
    }
}

// ---------------- CSR build (multi-block scan) -----------------------------------
__global__ void deg_kernel(const int* __restrict__ dst) {
    int e = blockIdx.x * blockDim.x + threadIdx.x;
    if (e >= T_EDGES) return;
    int d = (e < E_EDGES) ? dst[e] : (e - E_EDGES);
    atomicAdd(&g_deg[d], 1);
}

__global__ void scanA_kernel() {
    __shared__ int wsum[32];
    int t = threadIdx.x, b = blockIdx.x;
    int i = b * 1024 + t;
    int lane = t & 31, wr = t >> 5;
    int v = (i < N_NODES) ? g_deg[i] : 0;
    int incl = v;
    #pragma unroll
    for (int d = 1; d < 32; d <<= 1) {
        int tt = __shfl_up_sync(0xffffffffu, incl, d);
        if (lane >= d) incl += tt;
    }
    if (lane == 31) wsum[wr] = incl;
    __syncthreads();
    if (wr == 0) {
        int wv = wsum[lane];
        #pragma unroll
        for (int d = 1; d < 32; d <<= 1) {
            int tt = __shfl_up_sync(0xffffffffu, wv, d);
            if (lane >= d) wv += tt;
        }
        wsum[lane] = wv;
    }
    __syncthreads();
    int base = (wr > 0) ? wsum[wr - 1] : 0;
    incl += base;
    if (i < N_NODES) g_loc[i] = incl;
    if (t == 1023) g_bsum[b] = incl;
}

__global__ void scanB_kernel() {
    int t = threadIdx.x;
    int v = (t < 30) ? g_bsum[t] : 0;
    int incl = v;
    #pragma unroll
    for (int d = 1; d < 32; d <<= 1) {
        int tt = __shfl_up_sync(0xffffffffu, incl, d);
        if (t >= d) incl += tt;
    }
    g_bsum[t] = incl - v;
    if (t == 31) g_off[N_NODES] = incl;
}

__global__ void scanC_kernel() {
    int i = blockIdx.x * 1024 + threadIdx.x;
    if (i >= N_NODES) return;
    int off = g_bsum[blockIdx.x] + g_loc[i] - g_deg[i];
    g_off[i] = off;
    g_cur[i] = off;
}

__global__ void scatter_kernel(const int* __restrict__ src,
                               const int* __restrict__ dst) {
    int e = blockIdx.x * blockDim.x + threadIdx.x;
    if (e >= T_EDGES) return;
    int s, d;
    if (e < E_EDGES) { s = src[e]; d = dst[e]; }
    else             { s = d = e - E_EDGES; }
    int pos = atomicAdd(&g_cur[d], 1);
    g_srcp[pos] = s;
}

// ---------------- segment softmax + aggregation (warp per node-head) ------------
__global__ __launch_bounds__(256) void aggr_kernel(const float* __restrict__ b_gat) {
    int gw = (blockIdx.x * 256 + threadIdx.x) >> 5;
    int lane = threadIdx.x & 31;
    if (gw >= N_NODES * HEADS) return;
    int n = gw >> 2, h = gw & 3;
    int beg = g_off[n], end = g_off[n + 1];
    float si = g_si[n * 4 + h];

    float m = -1e30f;
    for (int j = beg + lane; j < end; j += 32) {
        int s = g_srcp[j];
        float a = si + g_sj[s * 4 + h];
        a = (a >= 0.f) ? a : NEG_SLOPE * a;
        m = fmaxf(m, a);
    }
    #pragma unroll
    for (int d = 16; d > 0; d >>= 1)
        m = fmaxf(m, __shfl_xor_sync(0xffffffffu, m, d));

    float den = 0.f, acc = 0.f;
    #pragma unroll 2
    for (int j = beg; j < end; j++) {
        int s = g_srcp[j];
        float a = si + g_sj[s * 4 + h];
        a = (a >= 0.f) ? a : NEG_SLOPE * a;
        float e = __expf(a - m);
        acc += e * g_C[(size_t)s * 256 + 128 + h * 32 + lane];
        den += e;
    }
    float r = acc / (den + 1e-16f) + b_gat[h * 32 + lane];
    g_gat[(size_t)n * HH + h * 32 + lane] = fmaxf(r, 0.f);
}

// ---------------- capsule + routing: 2 nodes/warp, per-class loop ----------------
#define CWARPS 16
#define WARP_FLOATS 784   // 528 (xc during pc-phase; tmp during routing) + 256 (u, 2 nodes)
#define CAP_SMEM_FLOATS (24576 + 512 + 16 + CWARPS * WARP_FLOATS + CWARPS * 12)

__device__ __forceinline__ float warp_sum32(float t) {
    t += __shfl_xor_sync(0xffffffffu, t, 1);
    t += __shfl_xor_sync(0xffffffffu, t, 2);
    t += __shfl_xor_sync(0xffffffffu, t, 4);
    t += __shfl_xor_sync(0xffffffffu, t, 8);
    t += __shfl_xor_sync(0xffffffffu, t, 16);
    return t;
}

__global__ __launch_bounds__(CWARPS * 32, 1)
void capsule_kernel(const float* __restrict__ Wp, const float* __restrict__ bp,
                    const float* __restrict__ route_w, const int* __restrict__ y,
                    float* __restrict__ out) {
    extern __shared__ float sh[];
    float4* rw4 = (float4*)sh;                         // 24576 floats (96KB)
    float* wps = sh + 24576;                           // 512
    float* bps = wps + 512;                            // 16
    float* warpb = bps + 16;                           // CWARPS * 784
    float* nshm  = warpb + CWARPS * WARP_FLOATS;       // CWARPS * 12
    __shared__ float blockLoss;

    int tid = threadIdx.x, lane = tid & 31, w = tid >> 5;

    // repack route_w: rw4[(pair*2+kq)*32 + lane] = {w[k..k+3] at o=lane}, k=4*kq
    for (int i4 = tid; i4 < 6144; i4 += CWARPS * 32) {
        int pair = i4 >> 6;
        int rem = i4 & 63;
        int kq = rem >> 5, ln = rem & 31;
        int base = (pair * 8 + kq * 4) * 32 + ln;
        rw4[i4] = make_float4(route_w[base], route_w[base + 32],
                              route_w[base + 64], route_w[base + 96]);
    }
    for (int i = tid; i < 512; i += CWARPS * 32) wps[i] = Wp[i];
    if (tid < 16) bps[tid] = bp[tid];
    if (tid == 0) blockLoss = 0.f;
    __syncthreads();

    float* xcw = warpb + w * WARP_FLOATS;   // 528: xc (2x264) then tmp (16x33)
    float* uwb = xcw + 528;                 // 256: u node0 [0:128), node1 [128:256)
    float* ncw = nshm + w * 12;

    for (int p = blockIdx.x * CWARPS + w; p < N_PAIRS; p += gridDim.x * CWARPS) {
        int n0 = 2 * p, n1 = 2 * p + 1;

        // ---- xc = relu(concat(gat, hidden)) for both nodes
        #pragma unroll
        for (int r = 0; r < 8; r++) {
            float v0 = (r < 4)
                ? g_gat[(size_t)n0 * HH + r * 32 + lane]
                : fmaxf(g_C[(size_t)n0 * 256 + (r - 4) * 32 + lane], 0.f);
            float v1 = (r < 4)
                ? g_gat[(size_t)n1 * HH + r * 32 + lane]
                : fmaxf(g_C[(size_t)n1 * 256 + (r - 4) * 32 + lane], 0.f);
            xcw[r * 33 + lane] = v0;
            xcw[264 + r * 33 + lane] = v1;
        }
        __syncwarp();

        // ---- primary capsules -> u (both nodes)
        #pragma unroll
        for (int nd = 0; nd < 2; nd++) {
            const float* xcn = xcw + nd * 264;
            float* uw = uwb + nd * 128;
            #pragma unroll
            for (int q = 0; q < 4; q++) {
                int idx = lane + 32 * q;
                int c = idx >> 6, r = (idx >> 3) & 7, o = idx & 7;
                float acc = bps[c * 8 + o];
                #pragma unroll
                for (int hh = 0; hh < 32; hh++)
                    acc += xcn[r * 33 + hh] * wps[(c * 32 + hh) * 8 + o];
                float t = acc * acc;
                t += __shfl_xor_sync(0xffffffffu, t, 1);
                t += __shfl_xor_sync(0xffffffffu, t, 2);
                t += __shfl_xor_sync(0xffffffffu, t, 4);
                uw[idx] = acc * sqrtf(t) / (1.f + t);
            }
        }
        __syncwarp();

        // ---- per-class priors + routing (lane = o)
        for (int c2 = 0; c2 < 6; c2++) {
            float pr0[16], pr1[16];
            #pragma unroll
            for (int rr = 0; rr < 16; rr++) {
                float4 a0 = *(const float4*)&uwb[rr * 8];
                float4 b0 = *(const float4*)&uwb[rr * 8 + 4];
                float4 a1 = *(const float4*)&uwb[128 + rr * 8];
                float4 b1 = *(const float4*)&uwb[128 + rr * 8 + 4];
                int pair = c2 * 16 + rr;
                float4 f0 = rw4[(pair * 2 + 0) * 32 + lane];
                float4 f1 = rw4[(pair * 2 + 1) * 32 + lane];
                pr0[rr] = a0.x * f0.x + a0.y * f0.y + a0.z * f0.z + a0.w * f0.w
                        + b0.x * f1.x + b0.y * f1.y + b0.z * f1.z + b0.w * f1.w;
                pr1[rr] = a1.x * f0.x + a1.y * f0.y + a1.z * f0.z + a1.w * f0.w
                        + b1.x * f1.x + b1.y * f1.y + b1.z * f1.z + b1.w * f1.w;
            }

            // it 0: probs uniform (logits = 0) -> v = mean_r priors
            float v0 = 0.f, v1 = 0.f;
            #pragma unroll
            for (int rr = 0; rr < 16; rr++) { v0 += pr0[rr]; v1 += pr1[rr]; }
            v0 *= 0.0625f; v1 *= 0.0625f;
            float sq0 = warp_sum32(v0 * v0);
            float sq1 = warp_sum32(v1 * v1);
            float vo0 = v0 * sqrtf(sq0) / (1.f + sq0);
            float vo1 = v1 * sqrtf(sq1) / (1.f + sq1);

            // logits distributed: lane l owns r=l&15 of node l>>4
            float bdist;
            __syncwarp();
            {
                #pragma unroll
                for (int rr = 0; rr < 16; rr++) xcw[rr * 33 + lane] = pr0[rr] * vo0;
                __syncwarp();
                const float* row = xcw + (lane & 15) * 33;
                float s0 = 0.f;
                #pragma unroll
                for (int o = 0; o < 32; o++) s0 += row[o];
                __syncwarp();
                #pragma unroll
                for (int rr = 0; rr < 16; rr++) xcw[rr * 33 + lane] = pr1[rr] * vo1;
                __syncwarp();
                float s1 = 0.f;
                #pragma unroll
                for (int o = 0; o < 32; o++) s1 += row[o];
                __syncwarp();
                bdist = (lane < 16) ? s0 : s1;
            }

            float norm0 = 0.f, norm1 = 0.f;
            #pragma unroll
            for (int it = 1; it < 3; it++) {
                // softmax over r (16-lane halves); no max-subtract (|b| <~ 50)
                float e = __expf(bdist);
                float es = e;
                es += __shfl_xor_sync(0xffffffffu, es, 1);
                es += __shfl_xor_sync(0xffffffffu, es, 2);
                es += __shfl_xor_sync(0xffffffffu, es, 4);
                es += __shfl_xor_sync(0xffffffffu, es, 8);
                float pp = __fdividef(e, es);
                v0 = 0.f; v1 = 0.f;
                #pragma unroll
                for (int rr = 0; rr < 16; rr++) {
                    float p0r = __shfl_sync(0xffffffffu, pp, rr);
                    float p1r = __shfl_sync(0xffffffffu, pp, 16 + rr);
                    v0 += p0r * pr0[rr];
                    v1 += p1r * pr1[rr];
                }
                sq0 = warp_sum32(v0 * v0);
                sq1 = warp_sum32(v1 * v1);
                vo0 = v0 * sqrtf(sq0) / (1.f + sq0);
                vo1 = v1 * sqrtf(sq1) / (1.f + sq1);
                if (it == 1) {
                    __syncwarp();
                    #pragma unroll
                    for (int rr = 0; rr < 16; rr++) xcw[rr * 33 + lane] = pr0[rr] * vo0;
                    __syncwarp();
                    const float* row = xcw + (lane & 15) * 33;
                    float s0 = 0.f;
                    #pragma unroll
                    for (int o = 0; o < 32; o++) s0 += row[o];
                    __syncwarp();
                    #pragma unroll
                    for (int rr = 0; rr < 16; rr++) xcw[rr * 33 + lane] = pr1[rr] * vo1;
                    __syncwarp();
                    float s1 = 0.f;
                    #pragma unroll
                    for (int o = 0; o < 32; o++) s1 += row[o];
                    __syncwarp();
                    bdist += (lane < 16) ? s0 : s1;
                } else {
                    norm0 = sq0 / (1.f + sq0);
                    norm1 = sq1 / (1.f + sq1);
                }
            }

            out[OUT_OFF_FEAT + (size_t)n0 * (NUM_LABEL * HDIM) + c2 * 32 + lane] = vo0;
            out[OUT_OFF_FEAT + (size_t)n1 * (NUM_LABEL * HDIM) + c2 * 32 + lane] = vo1;
            if (lane == 0) { ncw[c2] = norm0; ncw[6 + c2] = norm1; }
        }
        __syncwarp();

        // ---- per-node log-softmax loss + normc output
        if (lane == 0 || lane == 16) {
            int n = (lane == 0) ? n0 : n1;
            const float* nc = ncw + (lane >> 4) * 6;
            float mx = nc[0];
            #pragma unroll
            for (int c = 1; c < 6; c++) mx = fmaxf(mx, nc[c]);
            float sm = 0.f;
            #pragma unroll
            for (int c = 0; c < 6; c++) sm += __expf(nc[c] - mx);
            float lse = mx + logf(sm);
            float sel = nc[y[n]];
            #pragma unroll
            for (int c = 0; c < 6; c++) out[(size_t)n * 6 + c] = nc[c];
            atomicAdd(&blockLoss, lse - sel);
        }
        __syncwarp();
    }
    __syncthreads();
    if (tid == 0) atomicAdd(&out[OUT_OFF_LOSS], blockLoss / (float)N_NODES);
}

// ---------------- launch ---------------------------------------------------------
extern "C" void kernel_launch(void* const* d_in, const int* in_sizes, int n_in,
                              void* d_out, int out_size) {
    const float* x       = (const float*)d_in[0];
    const float* gamma   = (const float*)d_in[1];
    const float* beta    = (const float*)d_in[2];
    const float* W_lin   = (const float*)d_in[3];
    const float* b_lin   = (const float*)d_in[4];
    const float* W_gat   = (const float*)d_in[5];
    const float* att     = (const float*)d_in[6];
    const float* b_gat   = (const float*)d_in[7];
    const float* Wp      = (const float*)d_in[8];
    const float* bp      = (const float*)d_in[9];
    const float* route_w = (const float*)d_in[10];
    const int*   eidx    = (const int*)d_in[11];
    const int*   y       = (const int*)d_in[12];
    float* out = (float*)d_out;

    const int* src = eidx;
    const int* dst = eidx + E_EDGES;

    init_kernel<<<(2 * FDIM + N_NODES + 256) / 256, 256>>>(out);
    stats_split_kernel<<<240, 256>>>(x);
    fold_all_kernel<<<256, 256>>>(W_lin, W_gat, b_lin, gamma, beta);

    gemm_mma_kernel<<<dim3(2, (N_NODES + 127) / 128), 256>>>(att);

    deg_kernel<<<(T_EDGES + 255) / 256, 256>>>(dst);
    scanA_kernel<<<30, 1024>>>();
    scanB_kernel<<<1, 32>>>();
    scanC_kernel<<<30, 1024>>>();
    scatter_kernel<<<(T_EDGES + 255) / 256, 256>>>(src, dst);
    aggr_kernel<<<(N_NODES * HEADS + 7) / 8, 256>>>(b_gat);

    static const size_t cap_smem = (size_t)CAP_SMEM_FLOATS * sizeof(float);
    cudaFuncSetAttribute(capsule_kernel,
                         cudaFuncAttributeMaxDynamicSharedMemorySize,
                         (int)cap_smem);
    capsule_kernel<<<148, CWARPS * 32, cap_smem>>>(Wp, bp, route_w, y, out);
}